// round 5
// baseline (speedup 1.0000x reference)
#include <cuda_runtime.h>
#include <cuda_fp16.h>
#include <cstdint>

#define H 128
#define NI_MAX 100000
#define NT_MAX 100000
#define E_MAX  800000
#define SCAN_B 1024

// ---------------- scratch (device globals; no allocation allowed) ----------
__device__ uint2    g_hh[(size_t)NI_MAX * 32]; // h_src fp16 [NI,128] (25.6MB)
__device__ float    g_asrc[NI_MAX];
__device__ float    g_adst[NT_MAX];
__device__ float    g_ev[E_MAX];               // exp(leakyrelu(alpha))
__device__ float    g_denom[NT_MAX];
__device__ int      g_cnt[NT_MAX];
__device__ int      g_off[NT_MAX];
__device__ int      g_fill[NT_MAX];
__device__ int      g_itmp[NT_MAX];            // inclusive scan temp
__device__ int      g_bsum[256];
__device__ int      g_boff[256];
__device__ int      g_srcs[E_MAX];             // CSR-sorted src ids
__device__ float    g_ews[E_MAX];              // CSR-sorted exp weights
__device__ float4   g_wvd[32];                 // W_taste^T @ att_dst
__device__ float    g_cd[1];                   // b_taste . att_dst
__device__ float    g_csum[H];
__device__ float    g_csq[H];
__device__ float4   g_scale[32];
__device__ float4   g_shift[32];

// ---------------- small helpers -------------------------------------------
__device__ __forceinline__ unsigned long long dup2(float a) {
    unsigned long long r; asm("mov.b64 %0, {%1, %1};" : "=l"(r) : "f"(a)); return r;
}
__device__ __forceinline__ unsigned long long pk2(float a, float b) {
    unsigned long long r; asm("mov.b64 %0, {%1, %2};" : "=l"(r) : "f"(a), "f"(b)); return r;
}
__device__ __forceinline__ void up2(unsigned long long v, float& a, float& b) {
    asm("mov.b64 {%0, %1}, %2;" : "=f"(a), "=f"(b) : "l"(v));
}
__device__ __forceinline__ void fma2(unsigned long long& d, unsigned long long a, unsigned long long b) {
    asm("fma.rn.f32x2 %0, %1, %2, %0;" : "+l"(d) : "l"(a), "l"(b));
}
__device__ __forceinline__ float getc(const float4& v, int i) {
    return i == 0 ? v.x : i == 1 ? v.y : i == 2 ? v.z : v.w;
}

// ---------------- Kz: zero per-call state ----------------------------------
__global__ void k_zero(int nt) {
    int i = blockIdx.x * blockDim.x + threadIdx.x;
    if (i < nt) {
        g_denom[i] = 0.f;
        g_cnt[i]   = 0;
    }
    if (i < H) {
        g_csum[i] = 0.f;
        g_csq[i]  = 0.f;
    }
}

// ---------------- K0: wv_dst = W_taste^T @ att_dst, c_dst = b.att ----------
__global__ void k_prep(const float* __restrict__ Wt_, const float* __restrict__ bt,
                       const float* __restrict__ attd) {
    int t = threadIdx.x;                       // 128 threads
    float s = 0.f;
    #pragma unroll 8
    for (int k = 0; k < H; k++) s += Wt_[k * H + t] * attd[k];
    ((float*)g_wvd)[t] = s;
    __shared__ float sh[H];
    sh[t] = bt[t] * attd[t];
    __syncthreads();
    for (int o = 64; o > 0; o >>= 1) {
        if (t < o) sh[t] += sh[t + o];
        __syncthreads();
    }
    if (t == 0) g_cd[0] = sh[0];
}

// ---------------- K1: h_src = x_ing @ W_ing^T + b ; a_src = h_src.att_src --
__global__ __launch_bounds__(256) void k_hsrc(
    const float* __restrict__ x, const float* __restrict__ W,
    const float* __restrict__ b, const float* __restrict__ att, int ni) {
    extern __shared__ float Wt[];              // [128][132] transposed, padded
    for (int i = threadIdx.x; i < H * H; i += blockDim.x) {
        int c = i >> 7, k = i & (H - 1);
        Wt[k * 132 + c] = W[i];
    }
    __syncthreads();

    int wid  = blockIdx.x * (blockDim.x >> 5) + (threadIdx.x >> 5);
    int lane = threadIdx.x & 31;
    int r0 = wid * 8;
    if (r0 >= ni) return;

    float4 bv = ((const float4*)b)[lane];
    float4 av = ((const float4*)att)[lane];
    unsigned long long a01[8], a23[8];
    unsigned long long b01 = pk2(bv.x, bv.y), b23 = pk2(bv.z, bv.w);
    #pragma unroll
    for (int j = 0; j < 8; j++) { a01[j] = b01; a23[j] = b23; }

    const ulonglong2* Wt2 = (const ulonglong2*)Wt;   // row stride 33 (x16B)

    for (int k = 0; k < H; k += 4) {
        float4 xb[8];
        #pragma unroll
        for (int j = 0; j < 8; j++) {
            int r = r0 + j; if (r >= ni) r = ni - 1;     // clamp tail
            xb[j] = *(const float4*)(x + (size_t)r * H + k);  // warp-broadcast
        }
        #pragma unroll
        for (int kk = 0; kk < 4; kk++) {
            ulonglong2 wv = Wt2[(k + kk) * 33 + lane];
            #pragma unroll
            for (int j = 0; j < 8; j++) {
                unsigned long long xx = dup2(getc(xb[j], kk));
                fma2(a01[j], xx, wv.x);
                fma2(a23[j], xx, wv.y);
            }
        }
    }
    #pragma unroll
    for (int j = 0; j < 8; j++) {
        int r = r0 + j;
        if (r >= ni) break;
        float h0, h1, h2, h3;
        up2(a01[j], h0, h1); up2(a23[j], h2, h3);
        __half2 p0 = __floats2half2_rn(h0, h1);
        __half2 p1 = __floats2half2_rn(h2, h3);
        uint2 pk;
        pk.x = *reinterpret_cast<unsigned*>(&p0);
        pk.y = *reinterpret_cast<unsigned*>(&p1);
        g_hh[(size_t)r * 32 + lane] = pk;
        float d = h0 * av.x + h1 * av.y + h2 * av.z + h3 * av.w;
        #pragma unroll
        for (int o = 16; o > 0; o >>= 1) d += __shfl_xor_sync(0xFFFFFFFFu, d, o);
        if (lane == 0) g_asrc[r] = d;
    }
}

// ---------------- K2: a_dst = x_taste @ wv_dst + c_dst (2 nodes/warp) ------
__global__ void k_adst(const float* __restrict__ xt, int nt) {
    int wid  = blockIdx.x * (blockDim.x >> 5) + (threadIdx.x >> 5);
    int lane = threadIdx.x & 31;
    int t0 = wid * 2;
    if (t0 >= nt) return;
    int t1 = t0 + 1;
    float4 wv = g_wvd[lane];
    float4 v0 = ((const float4*)xt)[(size_t)t0 * 32 + lane];
    float d0 = v0.x * wv.x + v0.y * wv.y + v0.z * wv.z + v0.w * wv.w;
    float d1 = 0.f;
    if (t1 < nt) {
        float4 v1 = ((const float4*)xt)[(size_t)t1 * 32 + lane];
        d1 = v1.x * wv.x + v1.y * wv.y + v1.z * wv.z + v1.w * wv.w;
    }
    #pragma unroll
    for (int o = 16; o > 0; o >>= 1) {
        d0 += __shfl_xor_sync(0xFFFFFFFFu, d0, o);
        d1 += __shfl_xor_sync(0xFFFFFFFFu, d1, o);
    }
    if (lane == 0) {
        float cd = g_cd[0];
        g_adst[t0] = d0 + cd;
        if (t1 < nt) g_adst[t1] = d1 + cd;
    }
}

// ---------------- K3: ev = exp(leakyrelu(a_src[s]+a_dst[d])); denom; count -
// Max-shift dropped: coef = e/denom is shift-invariant; |alpha| < ~10.
__global__ void k_edge(const int* __restrict__ ei, int E_, int ni, int nt) {
    int e = blockIdx.x * blockDim.x + threadIdx.x;
    if (e >= E_) return;
    int s = ei[e];
    int d = ei[E_ + e];
    if ((unsigned)s >= (unsigned)ni || (unsigned)d >= (unsigned)nt) return;  // guard
    float al = g_asrc[s] + g_adst[d];
    al = al > 0.f ? al : 0.2f * al;
    float ev = __expf(al);
    g_ev[e] = ev;
    atomicAdd(&g_denom[d], ev);
    atomicAdd(&g_cnt[d], 1);
}

// ---------------- scan (counting-sort offsets) -----------------------------
__global__ void k_scan1(int n) {
    __shared__ int sh[SCAN_B];
    int i = blockIdx.x * SCAN_B + threadIdx.x;
    int v = (i < n) ? g_cnt[i] : 0;
    sh[threadIdx.x] = v;
    __syncthreads();
    for (int o = 1; o < SCAN_B; o <<= 1) {
        int t = (threadIdx.x >= o) ? sh[threadIdx.x - o] : 0;
        __syncthreads();
        sh[threadIdx.x] += t;
        __syncthreads();
    }
    if (i < n) g_itmp[i] = sh[threadIdx.x];
    if (threadIdx.x == SCAN_B - 1) g_bsum[blockIdx.x] = sh[threadIdx.x];
}
__global__ void k_scan2(int nb) {
    __shared__ int sh[256];
    int t = threadIdx.x;
    int v = (t < nb) ? g_bsum[t] : 0;
    sh[t] = v;
    __syncthreads();
    for (int o = 1; o < 256; o <<= 1) {
        int x = (t >= o) ? sh[t - o] : 0;
        __syncthreads();
        sh[t] += x;
        __syncthreads();
    }
    g_boff[t] = sh[t] - v;                    // exclusive
}
__global__ void k_scan3(int n) {
    int i = blockIdx.x * SCAN_B + threadIdx.x;
    if (i >= n) return;
    int off = g_itmp[i] - g_cnt[i] + g_boff[blockIdx.x];
    g_off[i]  = off;
    g_fill[i] = off;
}

// ---------------- K5: scatter edges into CSR order -------------------------
__global__ void k_scatter(const int* __restrict__ ei, int E_, int ni, int nt) {
    int e = blockIdx.x * blockDim.x + threadIdx.x;
    if (e >= E_) return;
    int s = ei[e];
    int d = ei[E_ + e];
    if ((unsigned)s >= (unsigned)ni || (unsigned)d >= (unsigned)nt) return;  // guard
    int pos = atomicAdd(&g_fill[d], 1);
    g_srcs[pos] = s;
    g_ews[pos]  = g_ev[e];
}

// ---------------- K6: agg = relu(sum coef*h); fused BN stats ---------------
__global__ __launch_bounds__(256) void k_agg(float* __restrict__ out, int nt, int nwarps) {
    int gw   = blockIdx.x * (blockDim.x >> 5) + (threadIdx.x >> 5);
    int lane = threadIdx.x & 31;
    float4 s4 = make_float4(0.f, 0.f, 0.f, 0.f);
    float4 q4 = make_float4(0.f, 0.f, 0.f, 0.f);

    for (int t = gw; t < nt; t += nwarps) {
        int n = g_cnt[t], off = g_off[t];
        float4 acc = make_float4(0.f, 0.f, 0.f, 0.f);
        if (n > 0) {
            float dinv = 1.0f / g_denom[t];
            int s = g_srcs[off];
            float w = g_ews[off];
            for (int j = 0; j < n; j++) {
                int s2 = 0; float w2 = 0.f;
                if (j + 1 < n) { s2 = g_srcs[off + j + 1]; w2 = g_ews[off + j + 1]; }
                uint2 p = g_hh[(size_t)s * 32 + lane];
                __half2 h01 = *reinterpret_cast<__half2*>(&p.x);
                __half2 h23 = *reinterpret_cast<__half2*>(&p.y);
                float2 f01 = __half22float2(h01);
                float2 f23 = __half22float2(h23);
                float c = w * dinv;
                acc.x += c * f01.x; acc.y += c * f01.y;
                acc.z += c * f23.x; acc.w += c * f23.y;
                s = s2; w = w2;
            }
        }
        acc.x = fmaxf(acc.x, 0.f); acc.y = fmaxf(acc.y, 0.f);
        acc.z = fmaxf(acc.z, 0.f); acc.w = fmaxf(acc.w, 0.f);
        ((float4*)out)[(size_t)t * 32 + lane] = acc;
        s4.x += acc.x; s4.y += acc.y; s4.z += acc.z; s4.w += acc.w;
        q4.x += acc.x * acc.x; q4.y += acc.y * acc.y;
        q4.z += acc.z * acc.z; q4.w += acc.w * acc.w;
    }
    int c0 = lane * 4;
    atomicAdd(&g_csum[c0 + 0], s4.x); atomicAdd(&g_csum[c0 + 1], s4.y);
    atomicAdd(&g_csum[c0 + 2], s4.z); atomicAdd(&g_csum[c0 + 3], s4.w);
    atomicAdd(&g_csq[c0 + 0], q4.x);  atomicAdd(&g_csq[c0 + 1], q4.y);
    atomicAdd(&g_csq[c0 + 2], q4.z);  atomicAdd(&g_csq[c0 + 3], q4.w);
}

// ---------------- K8: BN scale/shift ---------------------------------------
__global__ void k_bnprep(const float* __restrict__ gamma, const float* __restrict__ beta,
                         float invn) {
    int c = threadIdx.x;
    float mu  = g_csum[c] * invn;
    float var = fmaxf(g_csq[c] * invn - mu * mu, 0.f);
    float rs  = rsqrtf(var + 1e-5f);
    float sc  = gamma[c] * rs;
    ((float*)g_scale)[c] = sc;
    ((float*)g_shift)[c] = beta[c] - mu * sc;
}

// ---------------- K9: out = relu(out*scale + shift) ------------------------
__global__ void k_bn(float* __restrict__ out, int nt) {
    int i = blockIdx.x * blockDim.x + threadIdx.x;     // float4 index
    if (i >= nt * 32) return;
    int lane = i & 31;
    float4 v  = ((float4*)out)[i];
    float4 sc = g_scale[lane];
    float4 sh = g_shift[lane];
    v.x = fmaxf(v.x * sc.x + sh.x, 0.f);
    v.y = fmaxf(v.y * sc.y + sh.y, 0.f);
    v.z = fmaxf(v.z * sc.z + sh.z, 0.f);
    v.w = fmaxf(v.w * sc.w + sh.w, 0.f);
    ((float4*)out)[i] = v;
}

// ---------------- host -----------------------------------------------------
extern "C" void kernel_launch(void* const* d_in, const int* in_sizes, int n_in,
                              void* d_out, int out_size) {
    const float* x_ing   = (const float*)d_in[0];
    const float* x_taste = (const float*)d_in[1];
    const int*   ei      = (const int*)d_in[2];          // int32 edge index
    const float* W_ing   = (const float*)d_in[3];
    const float* b_ing   = (const float*)d_in[4];
    const float* W_taste = (const float*)d_in[5];
    const float* b_taste = (const float*)d_in[6];
    const float* att_src = (const float*)d_in[7];
    const float* att_dst = (const float*)d_in[8];
    // d_in[9..11] = k_lin_W, k_lin_b, q — unused (softmax over 1 metapath == 1.0)
    const float* gamma   = (const float*)d_in[12];
    const float* beta    = (const float*)d_in[13];

    int ni = in_sizes[0] / H;
    int nt = in_sizes[1] / H;
    int E_ = in_sizes[2] / 2;
    float* out = (float*)d_out;

    k_zero<<<(nt + 255) / 256, 256>>>(nt);

    const int smemW = 128 * 132 * 4;   // 67.6 KB
    cudaFuncSetAttribute(k_hsrc, cudaFuncAttributeMaxDynamicSharedMemorySize, smemW);

    k_prep<<<1, 128>>>(W_taste, b_taste, att_dst);

    int tasks = (ni + 7) / 8;
    k_hsrc<<<(tasks + 7) / 8, 256, smemW>>>(x_ing, W_ing, b_ing, att_src, ni);
    k_adst<<<(nt / 2 + 7) / 8 + 1, 256>>>(x_taste, nt);

    int eb = (E_ + 255) / 256;
    k_edge<<<eb, 256>>>(ei, E_, ni, nt);

    int nb = (nt + SCAN_B - 1) / SCAN_B;
    k_scan1<<<nb, SCAN_B>>>(nt);
    k_scan2<<<1, 256>>>(nb);
    k_scan3<<<nb, SCAN_B>>>(nt);
    k_scatter<<<eb, 256>>>(ei, E_, ni, nt);

    int aggBlocks = 592;                                  // 148 SMs x 4
    k_agg<<<aggBlocks, 256>>>(out, nt, aggBlocks * 8);
    k_bnprep<<<1, 128>>>(gamma, beta, 1.0f / (float)nt);
    k_bn<<<(nt * 32 + 255) / 256, 256>>>(out, nt);
}

// round 6
// speedup vs baseline: 1.2678x; 1.2678x over previous
#include <cuda_runtime.h>
#include <cuda_fp16.h>
#include <cstdint>

#define H 128
#define NI_MAX 100000
#define NT_MAX 100000
#define E_MAX  800000
#define SCAN_B 1024

// ---------------- scratch (device globals; no allocation allowed) ----------
__device__ uint2    g_hh[(size_t)NI_MAX * 32]; // h_src fp16 [NI,128] (25.6MB)
__device__ float    g_asrc[NI_MAX];
__device__ float    g_adst[NT_MAX];
__device__ float    g_ev[E_MAX];               // exp(leakyrelu(alpha))
__device__ float    g_denom[NT_MAX];
__device__ int      g_cnt[NT_MAX];
__device__ int      g_off[NT_MAX];
__device__ int      g_fill[NT_MAX];
__device__ int      g_itmp[NT_MAX];            // inclusive scan temp
__device__ int      g_bsum[256];
__device__ int      g_boff[256];
__device__ int      g_srcs[E_MAX];             // CSR-sorted src ids
__device__ float    g_ews[E_MAX];              // CSR-sorted exp weights
__device__ float4   g_wvd[32];                 // W_taste^T @ att_dst
__device__ float    g_cd[1];                   // b_taste . att_dst
__device__ float    g_csum[H];
__device__ float    g_csq[H];
__device__ float4   g_scale[32];
__device__ float4   g_shift[32];

// ---------------- small helpers -------------------------------------------
__device__ __forceinline__ unsigned long long dup2(float a) {
    unsigned long long r; asm("mov.b64 %0, {%1, %1};" : "=l"(r) : "f"(a)); return r;
}
__device__ __forceinline__ unsigned long long pk2(float a, float b) {
    unsigned long long r; asm("mov.b64 %0, {%1, %2};" : "=l"(r) : "f"(a), "f"(b)); return r;
}
__device__ __forceinline__ void up2(unsigned long long v, float& a, float& b) {
    asm("mov.b64 {%0, %1}, %2;" : "=f"(a), "=f"(b) : "l"(v));
}
__device__ __forceinline__ void fma2(unsigned long long& d, unsigned long long a, unsigned long long b) {
    asm("fma.rn.f32x2 %0, %1, %2, %0;" : "+l"(d) : "l"(a), "l"(b));
}
__device__ __forceinline__ float getc(const float4& v, int i) {
    return i == 0 ? v.x : i == 1 ? v.y : i == 2 ? v.z : v.w;
}

// ---------------- Kz: zero per-call state ----------------------------------
__global__ void k_zero(int nt) {
    int i = blockIdx.x * blockDim.x + threadIdx.x;
    if (i < nt) {
        g_denom[i] = 0.f;
        g_cnt[i]   = 0;
    }
    if (i < H) {
        g_csum[i] = 0.f;
        g_csq[i]  = 0.f;
    }
}

// ---------------- K0: wv_dst = W_taste^T @ att_dst, c_dst = b.att ----------
__global__ void k_prep(const float* __restrict__ Wt_, const float* __restrict__ bt,
                       const float* __restrict__ attd) {
    int t = threadIdx.x;                       // 128 threads
    float s = 0.f;
    #pragma unroll 8
    for (int k = 0; k < H; k++) s += Wt_[k * H + t] * attd[k];
    ((float*)g_wvd)[t] = s;
    __shared__ float sh[H];
    sh[t] = bt[t] * attd[t];
    __syncthreads();
    for (int o = 64; o > 0; o >>= 1) {
        if (t < o) sh[t] += sh[t + o];
        __syncthreads();
    }
    if (t == 0) g_cd[0] = sh[0];
}

// ---------------- K1: h_src = x_ing @ W_ing^T + b ; a_src = h_src.att_src --
__global__ __launch_bounds__(256) void k_hsrc(
    const float* __restrict__ x, const float* __restrict__ W,
    const float* __restrict__ b, const float* __restrict__ att, int ni) {
    extern __shared__ float Wt[];              // [128][132] transposed, padded
    for (int i = threadIdx.x; i < H * H; i += blockDim.x) {
        int c = i >> 7, k = i & (H - 1);
        Wt[k * 132 + c] = W[i];
    }
    __syncthreads();

    int wid  = blockIdx.x * (blockDim.x >> 5) + (threadIdx.x >> 5);
    int lane = threadIdx.x & 31;
    int r0 = wid * 8;
    if (r0 >= ni) return;

    float4 bv = ((const float4*)b)[lane];
    float4 av = ((const float4*)att)[lane];
    unsigned long long a01[8], a23[8];
    unsigned long long b01 = pk2(bv.x, bv.y), b23 = pk2(bv.z, bv.w);
    #pragma unroll
    for (int j = 0; j < 8; j++) { a01[j] = b01; a23[j] = b23; }

    const ulonglong2* Wt2 = (const ulonglong2*)Wt;   // row stride 33 (x16B)

    for (int k = 0; k < H; k += 4) {
        float4 xb[8];
        #pragma unroll
        for (int j = 0; j < 8; j++) {
            int r = r0 + j; if (r >= ni) r = ni - 1;     // clamp tail
            xb[j] = *(const float4*)(x + (size_t)r * H + k);  // warp-broadcast
        }
        #pragma unroll
        for (int kk = 0; kk < 4; kk++) {
            ulonglong2 wv = Wt2[(k + kk) * 33 + lane];
            #pragma unroll
            for (int j = 0; j < 8; j++) {
                unsigned long long xx = dup2(getc(xb[j], kk));
                fma2(a01[j], xx, wv.x);
                fma2(a23[j], xx, wv.y);
            }
        }
    }
    #pragma unroll
    for (int j = 0; j < 8; j++) {
        int r = r0 + j;
        if (r >= ni) break;
        float h0, h1, h2, h3;
        up2(a01[j], h0, h1); up2(a23[j], h2, h3);
        __half2 p0 = __floats2half2_rn(h0, h1);
        __half2 p1 = __floats2half2_rn(h2, h3);
        uint2 pk;
        pk.x = *reinterpret_cast<unsigned*>(&p0);
        pk.y = *reinterpret_cast<unsigned*>(&p1);
        g_hh[(size_t)r * 32 + lane] = pk;
        float d = h0 * av.x + h1 * av.y + h2 * av.z + h3 * av.w;
        #pragma unroll
        for (int o = 16; o > 0; o >>= 1) d += __shfl_xor_sync(0xFFFFFFFFu, d, o);
        if (lane == 0) g_asrc[r] = d;
    }
}

// ---------------- K2: a_dst = x_taste @ wv_dst + c_dst (2 nodes/warp) ------
__global__ void k_adst(const float* __restrict__ xt, int nt) {
    int wid  = blockIdx.x * (blockDim.x >> 5) + (threadIdx.x >> 5);
    int lane = threadIdx.x & 31;
    int t0 = wid * 2;
    if (t0 >= nt) return;
    int t1 = t0 + 1;
    float4 wv = g_wvd[lane];
    float4 v0 = ((const float4*)xt)[(size_t)t0 * 32 + lane];
    float d0 = v0.x * wv.x + v0.y * wv.y + v0.z * wv.z + v0.w * wv.w;
    float d1 = 0.f;
    if (t1 < nt) {
        float4 v1 = ((const float4*)xt)[(size_t)t1 * 32 + lane];
        d1 = v1.x * wv.x + v1.y * wv.y + v1.z * wv.z + v1.w * wv.w;
    }
    #pragma unroll
    for (int o = 16; o > 0; o >>= 1) {
        d0 += __shfl_xor_sync(0xFFFFFFFFu, d0, o);
        d1 += __shfl_xor_sync(0xFFFFFFFFu, d1, o);
    }
    if (lane == 0) {
        float cd = g_cd[0];
        g_adst[t0] = d0 + cd;
        if (t1 < nt) g_adst[t1] = d1 + cd;
    }
}

// ---------------- K3: ev = exp(leakyrelu(a_src[s]+a_dst[d])); denom; count -
// Max-shift dropped: coef = e/denom is shift-invariant; |alpha| < ~10.
__global__ void k_edge(const int* __restrict__ ei, int E_, int ni, int nt) {
    int e = blockIdx.x * blockDim.x + threadIdx.x;
    if (e >= E_) return;
    int s = ei[e];
    int d = ei[E_ + e];
    if ((unsigned)s >= (unsigned)ni || (unsigned)d >= (unsigned)nt) return;  // guard
    float al = g_asrc[s] + g_adst[d];
    al = al > 0.f ? al : 0.2f * al;
    float ev = __expf(al);
    g_ev[e] = ev;
    atomicAdd(&g_denom[d], ev);
    atomicAdd(&g_cnt[d], 1);
}

// ---------------- scan (counting-sort offsets) -----------------------------
__global__ void k_scan1(int n) {
    __shared__ int sh[SCAN_B];
    int i = blockIdx.x * SCAN_B + threadIdx.x;
    int v = (i < n) ? g_cnt[i] : 0;
    sh[threadIdx.x] = v;
    __syncthreads();
    for (int o = 1; o < SCAN_B; o <<= 1) {
        int t = (threadIdx.x >= o) ? sh[threadIdx.x - o] : 0;
        __syncthreads();
        sh[threadIdx.x] += t;
        __syncthreads();
    }
    if (i < n) g_itmp[i] = sh[threadIdx.x];
    if (threadIdx.x == SCAN_B - 1) g_bsum[blockIdx.x] = sh[threadIdx.x];
}
__global__ void k_scan2(int nb) {
    __shared__ int sh[256];
    int t = threadIdx.x;
    int v = (t < nb) ? g_bsum[t] : 0;
    sh[t] = v;
    __syncthreads();
    for (int o = 1; o < 256; o <<= 1) {
        int x = (t >= o) ? sh[t - o] : 0;
        __syncthreads();
        sh[t] += x;
        __syncthreads();
    }
    g_boff[t] = sh[t] - v;                    // exclusive
}
__global__ void k_scan3(int n) {
    int i = blockIdx.x * SCAN_B + threadIdx.x;
    if (i >= n) return;
    int off = g_itmp[i] - g_cnt[i] + g_boff[blockIdx.x];
    g_off[i]  = off;
    g_fill[i] = off;
}

// ---------------- K5: scatter edges into CSR order -------------------------
__global__ void k_scatter(const int* __restrict__ ei, int E_, int ni, int nt) {
    int e = blockIdx.x * blockDim.x + threadIdx.x;
    if (e >= E_) return;
    int s = ei[e];
    int d = ei[E_ + e];
    if ((unsigned)s >= (unsigned)ni || (unsigned)d >= (unsigned)nt) return;  // guard
    int pos = atomicAdd(&g_fill[d], 1);
    g_srcs[pos] = s;
    g_ews[pos]  = g_ev[e];
}

// ---------------- K6: agg[t] = relu( sum coef * h_src[s] ), one warp/node --
__global__ __launch_bounds__(256) void k_agg(float* __restrict__ out, int nt) {
    int wid  = blockIdx.x * (blockDim.x >> 5) + (threadIdx.x >> 5);
    int lane = threadIdx.x & 31;
    if (wid >= nt) return;
    int n = g_cnt[wid], off = g_off[wid];
    float4 acc = make_float4(0.f, 0.f, 0.f, 0.f);
    if (n > 0) {
        float dinv = 1.0f / g_denom[wid];
        int s = g_srcs[off];
        float w = g_ews[off];
        for (int j = 0; j < n; j++) {
            int s2 = 0; float w2 = 0.f;
            if (j + 1 < n) { s2 = g_srcs[off + j + 1]; w2 = g_ews[off + j + 1]; }
            uint2 p = g_hh[(size_t)s * 32 + lane];
            __half2 h01 = *reinterpret_cast<__half2*>(&p.x);
            __half2 h23 = *reinterpret_cast<__half2*>(&p.y);
            float2 f01 = __half22float2(h01);
            float2 f23 = __half22float2(h23);
            float c = w * dinv;
            acc.x += c * f01.x; acc.y += c * f01.y;
            acc.z += c * f23.x; acc.w += c * f23.y;
            s = s2; w = w2;
        }
    }
    acc.x = fmaxf(acc.x, 0.f); acc.y = fmaxf(acc.y, 0.f);
    acc.z = fmaxf(acc.z, 0.f); acc.w = fmaxf(acc.w, 0.f);
    ((float4*)out)[(size_t)wid * 32 + lane] = acc;
}

// ---------------- K7: per-column sums for BN -------------------------------
__global__ void k_stats(const float* __restrict__ out, int nt) {
    int c = threadIdx.x;                       // 128 threads = 128 columns
    float s = 0.f, q = 0.f;
    for (int r = blockIdx.x; r < nt; r += gridDim.x) {
        float v = out[(size_t)r * H + c];
        s += v; q += v * v;
    }
    atomicAdd(&g_csum[c], s);
    atomicAdd(&g_csq[c], q);
}

// ---------------- K8: BN scale/shift ---------------------------------------
__global__ void k_bnprep(const float* __restrict__ gamma, const float* __restrict__ beta,
                         float invn) {
    int c = threadIdx.x;
    float mu  = g_csum[c] * invn;
    float var = fmaxf(g_csq[c] * invn - mu * mu, 0.f);
    float rs  = rsqrtf(var + 1e-5f);
    float sc  = gamma[c] * rs;
    ((float*)g_scale)[c] = sc;
    ((float*)g_shift)[c] = beta[c] - mu * sc;
}

// ---------------- K9: out = relu(out*scale + shift) ------------------------
__global__ void k_bn(float* __restrict__ out, int nt) {
    int i = blockIdx.x * blockDim.x + threadIdx.x;     // float4 index
    if (i >= nt * 32) return;
    int lane = i & 31;
    float4 v  = ((float4*)out)[i];
    float4 sc = g_scale[lane];
    float4 sh = g_shift[lane];
    v.x = fmaxf(v.x * sc.x + sh.x, 0.f);
    v.y = fmaxf(v.y * sc.y + sh.y, 0.f);
    v.z = fmaxf(v.z * sc.z + sh.z, 0.f);
    v.w = fmaxf(v.w * sc.w + sh.w, 0.f);
    ((float4*)out)[i] = v;
}

// ---------------- host -----------------------------------------------------
extern "C" void kernel_launch(void* const* d_in, const int* in_sizes, int n_in,
                              void* d_out, int out_size) {
    const float* x_ing   = (const float*)d_in[0];
    const float* x_taste = (const float*)d_in[1];
    const int*   ei      = (const int*)d_in[2];          // int32 edge index
    const float* W_ing   = (const float*)d_in[3];
    const float* b_ing   = (const float*)d_in[4];
    const float* W_taste = (const float*)d_in[5];
    const float* b_taste = (const float*)d_in[6];
    const float* att_src = (const float*)d_in[7];
    const float* att_dst = (const float*)d_in[8];
    // d_in[9..11] = k_lin_W, k_lin_b, q — unused (softmax over 1 metapath == 1.0)
    const float* gamma   = (const float*)d_in[12];
    const float* beta    = (const float*)d_in[13];

    int ni = in_sizes[0] / H;
    int nt = in_sizes[1] / H;
    int E_ = in_sizes[2] / 2;
    float* out = (float*)d_out;

    k_zero<<<(nt + 255) / 256, 256>>>(nt);

    const int smemW = 128 * 132 * 4;   // 67.6 KB
    cudaFuncSetAttribute(k_hsrc, cudaFuncAttributeMaxDynamicSharedMemorySize, smemW);

    k_prep<<<1, 128>>>(W_taste, b_taste, att_dst);

    int tasks = (ni + 7) / 8;
    k_hsrc<<<(tasks + 7) / 8, 256, smemW>>>(x_ing, W_ing, b_ing, att_src, ni);
    k_adst<<<(nt / 2 + 7) / 8 + 1, 256>>>(x_taste, nt);

    int eb = (E_ + 255) / 256;
    k_edge<<<eb, 256>>>(ei, E_, ni, nt);

    int nb = (nt + SCAN_B - 1) / SCAN_B;
    k_scan1<<<nb, SCAN_B>>>(nt);
    k_scan2<<<1, 256>>>(nb);
    k_scan3<<<nb, SCAN_B>>>(nt);
    k_scatter<<<eb, 256>>>(ei, E_, ni, nt);

    k_agg<<<(nt + 7) / 8, 256>>>(out, nt);
    k_stats<<<1184, 128>>>(out, nt);
    k_bnprep<<<1, 128>>>(gamma, beta, 1.0f / (float)nt);
    k_bn<<<(nt * 32 + 255) / 256, 256>>>(out, nt);
}